// round 9
// baseline (speedup 1.0000x reference)
#include <cuda_runtime.h>
#include <cuda_bf16.h>

#define BB 8
#define NN 4096
#define KNN 20
#define CAT 320
#define KTILE 2048

typedef unsigned long long ull;

// packed f32x2 helpers (proven in local2_kernel, R7 pass)
#define FMA2(acc, a, b) asm("fma.rn.f32x2 %0, %1, %2, %0;" : "+l"(acc) : "l"(a), "l"(b))
__device__ __forceinline__ ull pack2(float lo, float hi) {
    ull r;
    asm("mov.b64 %0, {%1, %2};" : "=l"(r) : "r"(__float_as_uint(lo)), "r"(__float_as_uint(hi)));
    return r;
}
__device__ __forceinline__ void unpack2(ull v, float& lo, float& hi) {
    unsigned a, b;
    asm("mov.b64 {%0, %1}, %2;" : "=r"(a), "=r"(b) : "l"(v));
    lo = __uint_as_float(a); hi = __uint_as_float(b);
}

// ---------------- scratch (static device globals; no allocation) ----------------
__device__ __align__(16) float d_ptsT[BB * NN * 4];            // [b][n][x,y,z,sq]
__device__ int d_idx[BB * NN * KNN];                           // knn indices
__device__ __align__(16) float d_cat[(size_t)BB * NN * CAT];   // concat features [b][n][320]
__device__ unsigned long long d_keys[BB * 1024];               // packed (val, ~n) for max/argmax
__device__ __align__(16) float4 d_wT4[160 * 512];              // local_w repacked (f32x2 local layer)

// ---------------- prep ----------------
__global__ void prep_points_kernel(const float* __restrict__ pts) {
    int i = blockIdx.x * blockDim.x + threadIdx.x;
    if (i < BB * NN) {
        int b = i / NN, n = i % NN;
        float x = pts[((size_t)b * 3 + 0) * NN + n];
        float y = pts[((size_t)b * 3 + 1) * NN + n];
        float z = pts[((size_t)b * 3 + 2) * NN + n];
        float sq = x * x + y * y + z * z;
        d_ptsT[i * 4 + 0] = x;
        d_ptsT[i * 4 + 1] = y;
        d_ptsT[i * 4 + 2] = z;
        d_ptsT[i * 4 + 3] = sq;
    }
    if (i < BB * 1024) d_keys[i] = 0ULL;
}

// local_w [1024][320] -> wT4[c2][t] = (w[t][2c2], w[t+512][2c2], w[t][2c2+1], w[t+512][2c2+1])
__global__ void prep_wT4_kernel(const float* __restrict__ lw) {
    int i = blockIdx.x * blockDim.x + threadIdx.x;  // over 160*512
    if (i < 160 * 512) {
        int c2 = i / 512, t = i % 512;
        d_wT4[i] = make_float4(lw[(size_t)t * 320 + 2 * c2],
                               lw[(size_t)(t + 512) * 320 + 2 * c2],
                               lw[(size_t)t * 320 + 2 * c2 + 1],
                               lw[(size_t)(t + 512) * 320 + 2 * c2 + 1]);
    }
}

// ---------------- kNN: tile candidates through 32 KB static smem (R7-exact) ----------------
__global__ __launch_bounds__(256) void knn_kernel() {
    __shared__ __align__(16) float4 ps[KTILE];  // 32 KB
    int b = blockIdx.y;
    int n = blockIdx.x * blockDim.x + threadIdx.x;

    const float4* src = (const float4*)(d_ptsT) + (size_t)b * NN;
    float4 q = src[n];

    float bd[KNN];
    int bi[KNN];
#pragma unroll
    for (int k = 0; k < KNN; k++) { bd[k] = __int_as_float(0x7f800000); bi[k] = 0x7fffffff; }
    float wv = __int_as_float(0x7f800000);
    int wp = 0;

    for (int tile = 0; tile < NN / KTILE; tile++) {
        __syncthreads();
        for (int t = threadIdx.x; t < KTILE; t += blockDim.x)
            ps[t] = src[tile * KTILE + t];
        __syncthreads();

        const int jbase = tile * KTILE;
        for (int jj = 0; jj < KTILE; jj++) {
            float4 p = ps[jj];
            float dot = q.x * p.x + q.y * p.y + q.z * p.z;
            float dist = q.w + p.w - 2.0f * dot;
            if (dist < wv) {
                int j = jbase + jj;
                bd[wp] = dist; bi[wp] = j;
                float nv = bd[0]; int np = 0; int ni = bi[0];
#pragma unroll
                for (int t = 1; t < KNN; t++) {
                    if (bd[t] > nv || (bd[t] == nv && bi[t] > ni)) { nv = bd[t]; np = t; ni = bi[t]; }
                }
                wv = nv; wp = np;
            }
        }
    }
    int* orow = d_idx + ((size_t)b * NN + n) * KNN;
#pragma unroll
    for (int k = 0; k < KNN; k++) orow[k] = bi[k];
}

// ---------------- EdgeConv: R7-exact arithmetic, G channel-groups per block ----------------
// Per (n,o) the fp op sequence is identical to the R7-passing kernel; only the
// mapping of points to warps changed (G groups share the block-wide barriers).
template <int CIN, int COUT, int XSTRIDE, int IN_OFF, int OUT_OFF, int PPB, bool FROM_PTS, int G>
__global__ __launch_bounds__(G * COUT) void edge_kernel(const float* __restrict__ w,
                                                        const float* __restrict__ sc,
                                                        const float* __restrict__ bi) {
    __shared__ float wd_s[COUT * (CIN + 1)];
    __shared__ __align__(16) float ctr_s[G][((CIN + 3) / 4) * 4];
    __shared__ __align__(16) float nb_s[G][KNN * CIN];

    const int b = blockIdx.y;
    const int tid = threadIdx.x;
    const int group = tid / COUT;
    const int o = tid % COUT;  // 0..COUT-1
    const int n0 = blockIdx.x * (G * PPB) + group * PPB;

    float w2r[CIN];
#pragma unroll
    for (int c = 0; c < CIN; c++) w2r[c] = w[(size_t)o * 2 * CIN + CIN + c];
    const float sr = sc[o];
    const float br = bi[o];

    for (int t = tid; t < COUT * CIN; t += G * COUT) {
        int oo = t / CIN, c = t % CIN;
        wd_s[oo * (CIN + 1) + c] = w[(size_t)oo * 2 * CIN + c] - w[(size_t)oo * 2 * CIN + CIN + c];
    }
    __syncthreads();

    const float* xin = (FROM_PTS ? d_ptsT : d_cat) + (size_t)b * NN * XSTRIDE + IN_OFF;
    float* out = d_cat + (size_t)b * NN * CAT + OUT_OFF;

    for (int p = 0; p < PPB; p++) {
        const int n = n0 + p;
        const int* idxrow = d_idx + ((size_t)b * NN + n) * KNN;

        if constexpr (CIN % 4 == 0) {
            constexpr int C4 = CIN / 4;
            for (int t = o; t < KNN * C4; t += COUT) {
                int k = t / C4, c4 = t % C4;
                int j = idxrow[k];
                ((float4*)nb_s[group])[t] = *(const float4*)(xin + (size_t)j * XSTRIDE + c4 * 4);
            }
            if (o < C4) ((float4*)ctr_s[group])[o] = *(const float4*)(xin + (size_t)n * XSTRIDE + o * 4);
        } else {
            for (int t = o; t < KNN * CIN; t += COUT) {
                int k = t / CIN, c = t % CIN;
                nb_s[group][t] = xin[(size_t)idxrow[k] * XSTRIDE + c];
            }
            if (o < CIN) ctr_s[group][o] = xin[(size_t)n * XSTRIDE + o];
        }
        __syncthreads();

        float a = 0.0f;
#pragma unroll
        for (int c = 0; c < CIN; c++) a = fmaf(wd_s[o * (CIN + 1) + c], ctr_s[group][c], a);

        float m = 0.0f;
#pragma unroll
        for (int k = 0; k < KNN; k++) {
            float acc = a;
            if constexpr (CIN % 4 == 0) {
                constexpr int C4 = CIN / 4;
#pragma unroll
                for (int c4 = 0; c4 < C4; c4++) {
                    float4 v = ((float4*)nb_s[group])[k * C4 + c4];
                    acc = fmaf(w2r[4 * c4 + 0], v.x, acc);
                    acc = fmaf(w2r[4 * c4 + 1], v.y, acc);
                    acc = fmaf(w2r[4 * c4 + 2], v.z, acc);
                    acc = fmaf(w2r[4 * c4 + 3], v.w, acc);
                }
            } else {
#pragma unroll
                for (int c = 0; c < CIN; c++) acc = fmaf(w2r[c], nb_s[group][k * CIN + c], acc);
            }
            float y = fmaxf(fmaf(sr, acc, br), 0.0f);
            m = fmaxf(m, y);
        }
        out[(size_t)n * CAT + o] = m;
        __syncthreads();
    }
}

// ---------------- local 1024x320 pointwise MLP + global max/argmax (f32x2, proven) ----------------
__global__ __launch_bounds__(512, 1) void local2_kernel(const float* __restrict__ ls,
                                                        const float* __restrict__ lb) {
    __shared__ __align__(16) ull xs2[16][CAT];  // 40 KB: interleaved point-pair features
    const int b = blockIdx.y;
    const int n0 = blockIdx.x * 32;
    const int t = threadIdx.x;

    const float* cat = d_cat + (size_t)b * NN * CAT;
    for (int item = t; item < 16 * 80; item += 512) {
        int p2 = item / 80, c4 = item % 80;
        int A = n0 + 2 * p2;
        float4 a4 = *(const float4*)(cat + (size_t)A * CAT + c4 * 4);
        float4 b4 = *(const float4*)(cat + (size_t)(A + 1) * CAT + c4 * 4);
        ull* dst = &xs2[p2][c4 * 4];
        *(float4*)(dst)     = make_float4(a4.x, b4.x, a4.y, b4.y);
        *(float4*)(dst + 2) = make_float4(a4.z, b4.z, a4.w, b4.w);
    }
    __syncthreads();

    ull acc[2][16];
#pragma unroll
    for (int j = 0; j < 2; j++)
#pragma unroll
        for (int p = 0; p < 16; p++) acc[j][p] = 0ULL;

    for (int c2 = 0; c2 < 160; c2++) {
        float4 wv = d_wT4[c2 * 512 + t];
        ull w00 = pack2(wv.x, wv.x);
        ull w10 = pack2(wv.y, wv.y);
        ull w01 = pack2(wv.z, wv.z);
        ull w11 = pack2(wv.w, wv.w);
#pragma unroll
        for (int p = 0; p < 16; p++) {
            ulonglong2 x = *(const ulonglong2*)&xs2[p][2 * c2];
            FMA2(acc[0][p], w00, x.x);
            FMA2(acc[0][p], w01, x.y);
            FMA2(acc[1][p], w10, x.x);
            FMA2(acc[1][p], w11, x.y);
        }
    }

#pragma unroll
    for (int j = 0; j < 2; j++) {
        int och = t + j * 512;
        float sv = ls[och], bv = lb[och];
        float best = -1.0f;
        int bn = n0;
#pragma unroll
        for (int p = 0; p < 16; p++) {
            float vA, vB;
            unpack2(acc[j][p], vA, vB);
            float a = fmaxf(fmaf(sv, vA, bv), 0.0f);
            float c = fmaxf(fmaf(sv, vB, bv), 0.0f);
            if (a > best) { best = a; bn = n0 + 2 * p; }
            if (c > best) { best = c; bn = n0 + 2 * p + 1; }
        }
        unsigned long long key =
            ((unsigned long long)__float_as_uint(best) << 32) |
            (unsigned long long)(0xFFFFFFFFu - (unsigned)bn);
        atomicMax(&d_keys[b * 1024 + och], key);
    }
}

// ---------------- head: decode glob + indices, 1024->512->256 ----------------
__global__ __launch_bounds__(512) void head_kernel(const float* __restrict__ gw0,
                                                   const float* __restrict__ gs0,
                                                   const float* __restrict__ gb0,
                                                   const float* __restrict__ gw1,
                                                   const float* __restrict__ gs1,
                                                   const float* __restrict__ gb1,
                                                   float* __restrict__ outp) {
    __shared__ float glob[1024];
    __shared__ float hb[512];
    const int b = blockIdx.x;
    const int t = threadIdx.x;

    for (int i = t; i < 1024; i += 512) {
        unsigned long long k = d_keys[b * 1024 + i];
        glob[i] = __uint_as_float((unsigned)(k >> 32));
        outp[2048 + b * 1024 + i] = (float)(0xFFFFFFFFu - (unsigned)(k & 0xFFFFFFFFull));
    }
    __syncthreads();

    {
        float acc = 0.0f;
        const float* wr = gw0 + (size_t)t * 1024;
        for (int c = 0; c < 1024; c++) acc = fmaf(wr[c], glob[c], acc);
        hb[t] = fmaxf(fmaf(gs0[t], acc, gb0[t]), 0.0f);
    }
    __syncthreads();

    if (t < 256) {
        float acc = 0.0f;
        const float* wr = gw1 + (size_t)t * 512;
        for (int c = 0; c < 512; c++) acc = fmaf(wr[c], hb[c], acc);
        outp[b * 256 + t] = fmaxf(fmaf(gs1[t], acc, gb1[t]), 0.0f);
    }
}

// ---------------- launch ----------------
extern "C" void kernel_launch(void* const* d_in, const int* in_sizes, int n_in,
                              void* d_out, int out_size) {
    const float* pts    = (const float*)d_in[0];
    const float* ec_w0  = (const float*)d_in[1];
    const float* ec_s0  = (const float*)d_in[2];
    const float* ec_b0  = (const float*)d_in[3];
    const float* ec_w1  = (const float*)d_in[4];
    const float* ec_s1  = (const float*)d_in[5];
    const float* ec_b1  = (const float*)d_in[6];
    const float* ec_w2  = (const float*)d_in[7];
    const float* ec_s2  = (const float*)d_in[8];
    const float* ec_b2  = (const float*)d_in[9];
    const float* ec_w3  = (const float*)d_in[10];
    const float* ec_s3  = (const float*)d_in[11];
    const float* ec_b3  = (const float*)d_in[12];
    const float* localw = (const float*)d_in[13];
    const float* locals = (const float*)d_in[14];
    const float* localb = (const float*)d_in[15];
    const float* g_w0   = (const float*)d_in[16];
    const float* g_s0   = (const float*)d_in[17];
    const float* g_b0   = (const float*)d_in[18];
    const float* g_w1   = (const float*)d_in[19];
    const float* g_s1   = (const float*)d_in[20];
    const float* g_b1   = (const float*)d_in[21];
    float* outp = (float*)d_out;

    prep_points_kernel<<<(BB * NN + 255) / 256, 256>>>(pts);
    prep_wT4_kernel<<<(160 * 512 + 255) / 256, 256>>>(localw);

    knn_kernel<<<dim3(NN / 256, BB), 256>>>();

    // G=4 groups of 64 channels (256-thread blocks), 8 points per group
    edge_kernel<3, 64, 4, 0, 0, 8, true, 4><<<dim3(NN / 32, BB), 256>>>(ec_w0, ec_s0, ec_b0);
    edge_kernel<64, 64, CAT, 0, 64, 8, false, 4><<<dim3(NN / 32, BB), 256>>>(ec_w1, ec_s1, ec_b1);
    edge_kernel<64, 64, CAT, 64, 128, 8, false, 4><<<dim3(NN / 32, BB), 256>>>(ec_w2, ec_s2, ec_b2);
    // G=2 groups of 128 channels (256-thread blocks), 8 points per group
    edge_kernel<64, 128, CAT, 128, 192, 8, false, 2><<<dim3(NN / 16, BB), 256>>>(ec_w3, ec_s3, ec_b3);

    local2_kernel<<<dim3(NN / 32, BB), 512>>>(locals, localb);

    head_kernel<<<BB, 512>>>(g_w0, g_s0, g_b0, g_w1, g_s1, g_b1, outp);
}

// round 13
// speedup vs baseline: 1.0891x; 1.0891x over previous
#include <cuda_runtime.h>
#include <cuda_bf16.h>

#define BB 8
#define NN 4096
#define KNN 20
#define CAT 320
#define KTILE 2048

typedef unsigned long long ull;

// packed f32x2 helpers (proven in local2_kernel, R7 pass)
#define FMA2(acc, a, b) asm("fma.rn.f32x2 %0, %1, %2, %0;" : "+l"(acc) : "l"(a), "l"(b))
__device__ __forceinline__ ull pack2(float lo, float hi) {
    ull r;
    asm("mov.b64 %0, {%1, %2};" : "=l"(r) : "r"(__float_as_uint(lo)), "r"(__float_as_uint(hi)));
    return r;
}
__device__ __forceinline__ void unpack2(ull v, float& lo, float& hi) {
    unsigned a, b;
    asm("mov.b64 {%0, %1}, %2;" : "=r"(a), "=r"(b) : "l"(v));
    lo = __uint_as_float(a); hi = __uint_as_float(b);
}

// ---------------- scratch (static device globals; no allocation) ----------------
__device__ __align__(16) float d_ptsT[BB * NN * 4];            // [b][n][x,y,z,sq]
__device__ int d_idx[BB * NN * KNN];                           // knn indices
__device__ __align__(16) float d_cat[(size_t)BB * NN * CAT];   // concat features [b][n][320]
__device__ unsigned long long d_keys[BB * 1024];               // packed (val, ~n) for max/argmax
__device__ __align__(16) float4 d_wT4[160 * 512];              // local_w repacked (f32x2 local layer)

// ---------------- prep ----------------
__global__ void prep_points_kernel(const float* __restrict__ pts) {
    int i = blockIdx.x * blockDim.x + threadIdx.x;
    if (i < BB * NN) {
        int b = i / NN, n = i % NN;
        float x = pts[((size_t)b * 3 + 0) * NN + n];
        float y = pts[((size_t)b * 3 + 1) * NN + n];
        float z = pts[((size_t)b * 3 + 2) * NN + n];
        float sq = x * x + y * y + z * z;
        d_ptsT[i * 4 + 0] = x;
        d_ptsT[i * 4 + 1] = y;
        d_ptsT[i * 4 + 2] = z;
        d_ptsT[i * 4 + 3] = sq;
    }
    if (i < BB * 1024) d_keys[i] = 0ULL;
}

// local_w [1024][320] -> wT4[c2][t] = (w[t][2c2], w[t+512][2c2], w[t][2c2+1], w[t+512][2c2+1])
__global__ void prep_wT4_kernel(const float* __restrict__ lw) {
    int i = blockIdx.x * blockDim.x + threadIdx.x;  // over 160*512
    if (i < 160 * 512) {
        int c2 = i / 512, t = i % 512;
        d_wT4[i] = make_float4(lw[(size_t)t * 320 + 2 * c2],
                               lw[(size_t)(t + 512) * 320 + 2 * c2],
                               lw[(size_t)t * 320 + 2 * c2 + 1],
                               lw[(size_t)(t + 512) * 320 + 2 * c2 + 1]);
    }
}

// ---------------- kNN: tile candidates through 32 KB static smem (R7-exact) ----------------
__global__ __launch_bounds__(256) void knn_kernel() {
    __shared__ __align__(16) float4 ps[KTILE];  // 32 KB
    int b = blockIdx.y;
    int n = blockIdx.x * blockDim.x + threadIdx.x;

    const float4* src = (const float4*)(d_ptsT) + (size_t)b * NN;
    float4 q = src[n];

    float bd[KNN];
    int bi[KNN];
#pragma unroll
    for (int k = 0; k < KNN; k++) { bd[k] = __int_as_float(0x7f800000); bi[k] = 0x7fffffff; }
    float wv = __int_as_float(0x7f800000);
    int wp = 0;

    for (int tile = 0; tile < NN / KTILE; tile++) {
        __syncthreads();
        for (int t = threadIdx.x; t < KTILE; t += blockDim.x)
            ps[t] = src[tile * KTILE + t];
        __syncthreads();

        const int jbase = tile * KTILE;
        for (int jj = 0; jj < KTILE; jj++) {
            float4 p = ps[jj];
            float dot = q.x * p.x + q.y * p.y + q.z * p.z;
            float dist = q.w + p.w - 2.0f * dot;
            if (dist < wv) {
                int j = jbase + jj;
                bd[wp] = dist; bi[wp] = j;
                float nv = bd[0]; int np = 0; int ni = bi[0];
#pragma unroll
                for (int t = 1; t < KNN; t++) {
                    if (bd[t] > nv || (bd[t] == nv && bi[t] > ni)) { nv = bd[t]; np = t; ni = bi[t]; }
                }
                wv = nv; wp = np;
            }
        }
    }
    int* orow = d_idx + ((size_t)b * NN + n) * KNN;
#pragma unroll
    for (int k = 0; k < KNN; k++) orow[k] = bi[k];
}

// ---------------- EdgeConv layer 1 (CIN=3): R7-exact ----------------
__global__ __launch_bounds__(64) void edge1_kernel(const float* __restrict__ w,
                                                   const float* __restrict__ sc,
                                                   const float* __restrict__ bi) {
    const int CIN = 3, COUT = 64, PPB = 16;
    __shared__ float wd_s[COUT * (CIN + 1)];
    __shared__ __align__(16) float ctr_s[4];
    __shared__ __align__(16) float nb_s[KNN * CIN];

    const int b = blockIdx.y;
    const int n0 = blockIdx.x * PPB;
    const int o = threadIdx.x;

    float w2r[CIN];
#pragma unroll
    for (int c = 0; c < CIN; c++) w2r[c] = w[(size_t)o * 2 * CIN + CIN + c];
    const float sr = sc[o];
    const float br = bi[o];

    for (int t = o; t < COUT * CIN; t += COUT) {
        int oo = t / CIN, c = t % CIN;
        wd_s[oo * (CIN + 1) + c] = w[(size_t)oo * 2 * CIN + c] - w[(size_t)oo * 2 * CIN + CIN + c];
    }
    __syncthreads();

    const float* xin = d_ptsT + (size_t)b * NN * 4;
    float* out = d_cat + (size_t)b * NN * CAT;

    for (int p = 0; p < PPB; p++) {
        const int n = n0 + p;
        const int* idxrow = d_idx + ((size_t)b * NN + n) * KNN;

        for (int t = o; t < KNN * CIN; t += COUT) {
            int k = t / CIN, c = t % CIN;
            nb_s[t] = xin[(size_t)idxrow[k] * 4 + c];
        }
        if (o < CIN) ctr_s[o] = xin[(size_t)n * 4 + o];
        __syncthreads();

        float a = 0.0f;
#pragma unroll
        for (int c = 0; c < CIN; c++) a = fmaf(wd_s[o * (CIN + 1) + c], ctr_s[c], a);

        float m = 0.0f;
#pragma unroll
        for (int k = 0; k < KNN; k++) {
            float acc = a;
#pragma unroll
            for (int c = 0; c < CIN; c++) acc = fmaf(w2r[c], nb_s[k * CIN + c], acc);
            float y = fmaxf(fmaf(sr, acc, br), 0.0f);
            m = fmaxf(m, y);
        }
        out[(size_t)n * CAT + o] = m;
        __syncthreads();
    }
}

// ---------------- EdgeConv layers 2-4 (CIN=64): software-pipelined gather ----------------
// Per (n,o) fp op sequence is byte-identical to the R7-passing kernel; only the
// gather for point p+1 is issued into registers before computing point p.
template <int COUT, int IN_OFF, int OUT_OFF, int PPB>
__global__ __launch_bounds__(COUT) void edge_pipe_kernel(const float* __restrict__ w,
                                                         const float* __restrict__ sc,
                                                         const float* __restrict__ bi) {
    constexpr int CIN = 64;
    constexpr int C4 = CIN / 4;                         // 16
    constexpr int NIT = (KNN * C4 + COUT - 1) / COUT;   // 5 (COUT=64) or 3 (COUT=128)
    __shared__ float wd_s[COUT * (CIN + 1)];
    __shared__ __align__(16) float nb_s[2][KNN * CIN];
    __shared__ __align__(16) float ctr_s[2][CIN];

    const int b = blockIdx.y;
    const int n0 = blockIdx.x * PPB;
    const int o = threadIdx.x;  // 0..COUT-1

    float w2r[CIN];
#pragma unroll
    for (int c = 0; c < CIN; c++) w2r[c] = w[(size_t)o * 2 * CIN + CIN + c];
    const float sr = sc[o];
    const float br = bi[o];

    for (int t = o; t < COUT * CIN; t += COUT) {
        int oo = t / CIN, c = t % CIN;
        wd_s[oo * (CIN + 1) + c] = w[(size_t)oo * 2 * CIN + c] - w[(size_t)oo * 2 * CIN + CIN + c];
    }

    const float* xin = d_cat + (size_t)b * NN * CAT + IN_OFF;
    float* out = d_cat + (size_t)b * NN * CAT + OUT_OFF;

    // prologue: gather point 0 into buffer 0 (R7-identical placement)
    {
        const int* idxrow = d_idx + ((size_t)b * NN + n0) * KNN;
        for (int t = o; t < KNN * C4; t += COUT) {
            int k = t / C4, c4 = t % C4;
            int j = idxrow[k];
            ((float4*)nb_s[0])[t] = *(const float4*)(xin + (size_t)j * CAT + c4 * 4);
        }
        if (o < C4) ((float4*)ctr_s[0])[o] = *(const float4*)(xin + (size_t)n0 * CAT + o * 4);
    }
    __syncthreads();

    for (int p = 0; p < PPB; p++) {
        const int cur = p & 1, nxt = cur ^ 1;
        const int n = n0 + p;

        // issue prefetch loads for point p+1 into registers (no consumer -> no stall)
        float4 v[NIT];
        float4 cv;
        if (p + 1 < PPB) {
            const int* idxn = d_idx + ((size_t)b * NN + n + 1) * KNN;
#pragma unroll
            for (int i = 0; i < NIT; i++) {
                int t = o + i * COUT;
                if (t < KNN * C4) {
                    int j = idxn[t / C4];
                    v[i] = *(const float4*)(xin + (size_t)j * CAT + (t % C4) * 4);
                }
            }
            if (o < C4) cv = *(const float4*)(xin + (size_t)(n + 1) * CAT + o * 4);
        }

        // compute point p (R7-exact sequence) — covers the prefetch latency
        float a = 0.0f;
#pragma unroll
        for (int c = 0; c < CIN; c++) a = fmaf(wd_s[o * (CIN + 1) + c], ctr_s[cur][c], a);

        float m = 0.0f;
#pragma unroll
        for (int k = 0; k < KNN; k++) {
            float acc = a;
#pragma unroll
            for (int c4 = 0; c4 < C4; c4++) {
                float4 x = ((float4*)nb_s[cur])[k * C4 + c4];
                acc = fmaf(w2r[4 * c4 + 0], x.x, acc);
                acc = fmaf(w2r[4 * c4 + 1], x.y, acc);
                acc = fmaf(w2r[4 * c4 + 2], x.z, acc);
                acc = fmaf(w2r[4 * c4 + 3], x.w, acc);
            }
            float y = fmaxf(fmaf(sr, acc, br), 0.0f);
            m = fmaxf(m, y);
        }
        out[(size_t)n * CAT + o] = m;

        // stage the prefetched data into the other buffer
        if (p + 1 < PPB) {
#pragma unroll
            for (int i = 0; i < NIT; i++) {
                int t = o + i * COUT;
                if (t < KNN * C4) ((float4*)nb_s[nxt])[t] = v[i];
            }
            if (o < C4) ((float4*)ctr_s[nxt])[o] = cv;
        }
        __syncthreads();
    }
}

// ---------------- local 1024x320 pointwise MLP + global max/argmax (f32x2, proven) ----------------
__global__ __launch_bounds__(512, 1) void local2_kernel(const float* __restrict__ ls,
                                                        const float* __restrict__ lb) {
    __shared__ __align__(16) ull xs2[16][CAT];  // 40 KB: interleaved point-pair features
    const int b = blockIdx.y;
    const int n0 = blockIdx.x * 32;
    const int t = threadIdx.x;

    const float* cat = d_cat + (size_t)b * NN * CAT;
    for (int item = t; item < 16 * 80; item += 512) {
        int p2 = item / 80, c4 = item % 80;
        int A = n0 + 2 * p2;
        float4 a4 = *(const float4*)(cat + (size_t)A * CAT + c4 * 4);
        float4 b4 = *(const float4*)(cat + (size_t)(A + 1) * CAT + c4 * 4);
        ull* dst = &xs2[p2][c4 * 4];
        *(float4*)(dst)     = make_float4(a4.x, b4.x, a4.y, b4.y);
        *(float4*)(dst + 2) = make_float4(a4.z, b4.z, a4.w, b4.w);
    }
    __syncthreads();

    ull acc[2][16];
#pragma unroll
    for (int j = 0; j < 2; j++)
#pragma unroll
        for (int p = 0; p < 16; p++) acc[j][p] = 0ULL;

    for (int c2 = 0; c2 < 160; c2++) {
        float4 wv = d_wT4[c2 * 512 + t];
        ull w00 = pack2(wv.x, wv.x);
        ull w10 = pack2(wv.y, wv.y);
        ull w01 = pack2(wv.z, wv.z);
        ull w11 = pack2(wv.w, wv.w);
#pragma unroll
        for (int p = 0; p < 16; p++) {
            ulonglong2 x = *(const ulonglong2*)&xs2[p][2 * c2];
            FMA2(acc[0][p], w00, x.x);
            FMA2(acc[0][p], w01, x.y);
            FMA2(acc[1][p], w10, x.x);
            FMA2(acc[1][p], w11, x.y);
        }
    }

#pragma unroll
    for (int j = 0; j < 2; j++) {
        int och = t + j * 512;
        float sv = ls[och], bv = lb[och];
        float best = -1.0f;
        int bn = n0;
#pragma unroll
        for (int p = 0; p < 16; p++) {
            float vA, vB;
            unpack2(acc[j][p], vA, vB);
            float a = fmaxf(fmaf(sv, vA, bv), 0.0f);
            float c = fmaxf(fmaf(sv, vB, bv), 0.0f);
            if (a > best) { best = a; bn = n0 + 2 * p; }
            if (c > best) { best = c; bn = n0 + 2 * p + 1; }
        }
        unsigned long long key =
            ((unsigned long long)__float_as_uint(best) << 32) |
            (unsigned long long)(0xFFFFFFFFu - (unsigned)bn);
        atomicMax(&d_keys[b * 1024 + och], key);
    }
}

// ---------------- head: decode glob + indices, 1024->512->256 ----------------
__global__ __launch_bounds__(512) void head_kernel(const float* __restrict__ gw0,
                                                   const float* __restrict__ gs0,
                                                   const float* __restrict__ gb0,
                                                   const float* __restrict__ gw1,
                                                   const float* __restrict__ gs1,
                                                   const float* __restrict__ gb1,
                                                   float* __restrict__ outp) {
    __shared__ float glob[1024];
    __shared__ float hb[512];
    const int b = blockIdx.x;
    const int t = threadIdx.x;

    for (int i = t; i < 1024; i += 512) {
        unsigned long long k = d_keys[b * 1024 + i];
        glob[i] = __uint_as_float((unsigned)(k >> 32));
        outp[2048 + b * 1024 + i] = (float)(0xFFFFFFFFu - (unsigned)(k & 0xFFFFFFFFull));
    }
    __syncthreads();

    {
        float acc = 0.0f;
        const float* wr = gw0 + (size_t)t * 1024;
        for (int c = 0; c < 1024; c++) acc = fmaf(wr[c], glob[c], acc);
        hb[t] = fmaxf(fmaf(gs0[t], acc, gb0[t]), 0.0f);
    }
    __syncthreads();

    if (t < 256) {
        float acc = 0.0f;
        const float* wr = gw1 + (size_t)t * 512;
        for (int c = 0; c < 512; c++) acc = fmaf(wr[c], hb[c], acc);
        outp[b * 256 + t] = fmaxf(fmaf(gs1[t], acc, gb1[t]), 0.0f);
    }
}

// ---------------- launch ----------------
extern "C" void kernel_launch(void* const* d_in, const int* in_sizes, int n_in,
                              void* d_out, int out_size) {
    const float* pts    = (const float*)d_in[0];
    const float* ec_w0  = (const float*)d_in[1];
    const float* ec_s0  = (const float*)d_in[2];
    const float* ec_b0  = (const float*)d_in[3];
    const float* ec_w1  = (const float*)d_in[4];
    const float* ec_s1  = (const float*)d_in[5];
    const float* ec_b1  = (const float*)d_in[6];
    const float* ec_w2  = (const float*)d_in[7];
    const float* ec_s2  = (const float*)d_in[8];
    const float* ec_b2  = (const float*)d_in[9];
    const float* ec_w3  = (const float*)d_in[10];
    const float* ec_s3  = (const float*)d_in[11];
    const float* ec_b3  = (const float*)d_in[12];
    const float* localw = (const float*)d_in[13];
    const float* locals = (const float*)d_in[14];
    const float* localb = (const float*)d_in[15];
    const float* g_w0   = (const float*)d_in[16];
    const float* g_s0   = (const float*)d_in[17];
    const float* g_b0   = (const float*)d_in[18];
    const float* g_w1   = (const float*)d_in[19];
    const float* g_s1   = (const float*)d_in[20];
    const float* g_b1   = (const float*)d_in[21];
    float* outp = (float*)d_out;

    prep_points_kernel<<<(BB * NN + 255) / 256, 256>>>(pts);

    knn_kernel<<<dim3(NN / 256, BB), 256>>>();

    edge1_kernel<<<dim3(NN / 16, BB), 64>>>(ec_w0, ec_s0, ec_b0);

    // pipelined CIN=64 layers (4th user launch = edge2, lands in the ncu capture slot)
    edge_pipe_kernel<64, 0, 64, 16><<<dim3(NN / 16, BB), 64>>>(ec_w1, ec_s1, ec_b1);

    prep_wT4_kernel<<<(160 * 512 + 255) / 256, 256>>>(localw);

    edge_pipe_kernel<64, 64, 128, 16><<<dim3(NN / 16, BB), 64>>>(ec_w2, ec_s2, ec_b2);
    edge_pipe_kernel<128, 128, 192, 16><<<dim3(NN / 16, BB), 128>>>(ec_w3, ec_s3, ec_b3);

    local2_kernel<<<dim3(NN / 32, BB), 512>>>(locals, localb);

    head_kernel<<<BB, 512>>>(g_w0, g_s0, g_b0, g_w1, g_s1, g_b1, outp);
}